// round 12
// baseline (speedup 1.0000x reference)
#include <cuda_runtime.h>
#include <math.h>

#define Bb 4
#define Nn 4096
#define Dd 256
#define BM 64
#define BN 64
#define QS 260   // q_s row stride (floats), padded vs 256 to split bank groups
#define PS 68    // p_s row stride (floats)
#define SCALE 0.17677669529663689f   // 32^-0.5 (head_dim scaling per reference)

// Scratch (static __device__ — no allocation allowed)
__device__ float g_invq[Bb * Nn];
__device__ float g_invk[Bb * Nn];
__device__ float g_kt[(size_t)Bb * Dd * Nn];   // K transposed: [b][d][key], pre-scaled by invk

// ---------------------------------------------------------------------------
// Kernel 1: per-row inverse L2 norms for Q and K.
// One warp per row (256 floats). invq gets SCALE folded in.
// ---------------------------------------------------------------------------
__global__ void row_invnorm_kernel(const float* __restrict__ Q,
                                   const float* __restrict__ K) {
    int gw   = (blockIdx.x * blockDim.x + threadIdx.x) >> 5;
    int lane = threadIdx.x & 31;
    if (gw >= 2 * Bb * Nn) return;
    bool isQ = gw < Bb * Nn;
    int row  = isQ ? gw : gw - Bb * Nn;
    const float* src = (isQ ? Q : K) + (size_t)row * Dd;

    float ss = 0.f;
#pragma unroll
    for (int c = lane * 4; c < Dd; c += 128) {
        float4 v = *(const float4*)(src + c);
        ss += v.x * v.x + v.y * v.y + v.z * v.z + v.w * v.w;
    }
#pragma unroll
    for (int off = 16; off; off >>= 1)
        ss += __shfl_xor_sync(0xffffffffu, ss, off);

    if (lane == 0) {
        float inv = 1.f / fmaxf(sqrtf(ss), 1e-12f);   // matches torch F.normalize eps
        if (isQ) g_invq[row] = inv * SCALE;
        else     g_invk[row] = inv;
    }
}

// ---------------------------------------------------------------------------
// Kernel 2: K[b][key][d] * invk[key]  ->  g_kt[b][d][key]   (32x32 smem tiles)
// Gives the attention mainloop fully-coalesced, conflict-free K tile loads.
// ---------------------------------------------------------------------------
__global__ void transpose_scale_kernel(const float* __restrict__ K) {
    __shared__ float tile[32][33];
    int b     = blockIdx.z;
    int cbase = blockIdx.x * 32;   // key dim
    int dbase = blockIdx.y * 32;   // feature dim
    int tx = threadIdx.x, ty = threadIdx.y;   // (32, 8)

#pragma unroll
    for (int j = 0; j < 32; j += 8) {
        int c = cbase + ty + j;
        tile[ty + j][tx] = K[((size_t)b * Nn + c) * Dd + dbase + tx] * g_invk[b * Nn + c];
    }
    __syncthreads();
#pragma unroll
    for (int j = 0; j < 32; j += 8) {
        int d = dbase + ty + j;
        g_kt[((size_t)b * Dd + d) * Nn + cbase + tx] = tile[tx][ty + j];
    }
}

// ---------------------------------------------------------------------------
// Kernel 3: flash attention, fp32 SIMT.
// Grid (Nn/BM, Bb), 256 threads. Thread (ty,tx) with ty=tid>>4, tx=tid&15:
//   S micro-tile: rows ty*4..+3, cols tx*4..+3
//   O micro-tile: rows ty*4..+3, cols tx*16..+15 (same 16-thread row group ->
//   softmax stats replicated per row group, no smem needed for m/l)
// ---------------------------------------------------------------------------
__global__ void __launch_bounds__(256, 1)
attn_kernel(const float* __restrict__ Q, const float* __restrict__ V,
            float* __restrict__ O) {
    extern __shared__ float smf[];
    float* q_s = smf;                    // BM x QS  (pre-scaled by invq*SCALE)
    float* k_s = q_s + BM * QS;          // Dd x BN  (d-major, pre-scaled by invk)
    float* v_s = k_s + Dd * BN;          // BN x Dd
    float* p_s = v_s + BN * Dd;          // BM x PS

    int tid = threadIdx.x;
    int tx = tid & 15, ty = tid >> 4;
    int b = blockIdx.y;
    int qbase = blockIdx.x * BM;

    // ---- load + scale Q tile ----
    {
        const float* qsrc = Q + ((size_t)b * Nn + qbase) * Dd;
#pragma unroll
        for (int i = 0; i < 16; ++i) {
            int j = tid + i * 256;          // float4 index over 64x64 grid
            int row = j >> 6, col4 = j & 63;
            float iv = g_invq[b * Nn + qbase + row];
            float4 v = *(const float4*)(qsrc + (size_t)row * Dd + col4 * 4);
            v.x *= iv; v.y *= iv; v.z *= iv; v.w *= iv;
            *(float4*)(q_s + row * QS + col4 * 4) = v;
        }
    }

    float4 o[4][4];
    float m[4], l[4];
#pragma unroll
    for (int i = 0; i < 4; ++i) {
        m[i] = -3.0e38f; l[i] = 0.f;
#pragma unroll
        for (int u = 0; u < 4; ++u) o[i][u] = make_float4(0.f, 0.f, 0.f, 0.f);
    }

    for (int t = 0; t < Nn / BN; ++t) {
        __syncthreads();   // previous tile's p_s/v_s reads done before overwrite

        // ---- load K (transposed, pre-scaled) and V tiles, fully coalesced ----
        {
            const float* ksrc = g_kt + (size_t)b * Dd * Nn + (size_t)t * BN;
#pragma unroll
            for (int i = 0; i < 16; ++i) {
                int j = tid + i * 256;      // float4 index over 256x16 grid
                int d = j >> 4, c4 = j & 15;
                *(float4*)(k_s + d * BN + c4 * 4) =
                    *(const float4*)(ksrc + (size_t)d * Nn + c4 * 4);
            }
            const float4* vsrc = (const float4*)(V + ((size_t)b * Nn + (size_t)t * BN) * Dd);
            float4* vdst = (float4*)v_s;
#pragma unroll
            for (int i = 0; i < 16; ++i) vdst[tid + i * 256] = vsrc[tid + i * 256];
        }
        __syncthreads();

        // ---- S = Q K^T (already fully scaled) ----
        float s[4][4];
#pragma unroll
        for (int i = 0; i < 4; ++i)
#pragma unroll
            for (int j = 0; j < 4; ++j) s[i][j] = 0.f;

#pragma unroll 4
        for (int d4 = 0; d4 < Dd / 4; ++d4) {
            float4 qv[4], kv[4];
#pragma unroll
            for (int i = 0; i < 4; ++i)
                qv[i] = *(const float4*)(q_s + (ty * 4 + i) * QS + d4 * 4);
#pragma unroll
            for (int dd = 0; dd < 4; ++dd)
                kv[dd] = *(const float4*)(k_s + (d4 * 4 + dd) * BN + tx * 4);
#pragma unroll
            for (int i = 0; i < 4; ++i) {
                float a0 = qv[i].x, a1 = qv[i].y, a2 = qv[i].z, a3 = qv[i].w;
                s[i][0] += a0 * kv[0].x; s[i][1] += a0 * kv[0].y; s[i][2] += a0 * kv[0].z; s[i][3] += a0 * kv[0].w;
                s[i][0] += a1 * kv[1].x; s[i][1] += a1 * kv[1].y; s[i][2] += a1 * kv[1].z; s[i][3] += a1 * kv[1].w;
                s[i][0] += a2 * kv[2].x; s[i][1] += a2 * kv[2].y; s[i][2] += a2 * kv[2].z; s[i][3] += a2 * kv[2].w;
                s[i][0] += a3 * kv[3].x; s[i][1] += a3 * kv[3].y; s[i][2] += a3 * kv[3].z; s[i][3] += a3 * kv[3].w;
            }
        }

        // ---- online softmax (row groups = 16 tx lanes, xor-shuffle reduce) ----
#pragma unroll
        for (int i = 0; i < 4; ++i) {
            float mx = fmaxf(fmaxf(s[i][0], s[i][1]), fmaxf(s[i][2], s[i][3]));
#pragma unroll
            for (int off = 8; off; off >>= 1)
                mx = fmaxf(mx, __shfl_xor_sync(0xffffffffu, mx, off));
            float mn = fmaxf(m[i], mx);
            float corr = __expf(m[i] - mn);
            m[i] = mn;
            s[i][0] = __expf(s[i][0] - mn);
            s[i][1] = __expf(s[i][1] - mn);
            s[i][2] = __expf(s[i][2] - mn);
            s[i][3] = __expf(s[i][3] - mn);
            float rs = s[i][0] + s[i][1] + s[i][2] + s[i][3];
#pragma unroll
            for (int off = 8; off; off >>= 1)
                rs += __shfl_xor_sync(0xffffffffu, rs, off);
            l[i] = l[i] * corr + rs;
#pragma unroll
            for (int u = 0; u < 4; ++u) {
                o[i][u].x *= corr; o[i][u].y *= corr;
                o[i][u].z *= corr; o[i][u].w *= corr;
            }
            *(float4*)(p_s + (ty * 4 + i) * PS + tx * 4) =
                make_float4(s[i][0], s[i][1], s[i][2], s[i][3]);
        }
        __syncthreads();

        // ---- O += P V ----
#pragma unroll 2
        for (int c = 0; c < BN; ++c) {
            float p0 = p_s[(ty * 4 + 0) * PS + c];
            float p1 = p_s[(ty * 4 + 1) * PS + c];
            float p2 = p_s[(ty * 4 + 2) * PS + c];
            float p3 = p_s[(ty * 4 + 3) * PS + c];
            const float* vr = v_s + c * Dd + tx * 16;
#pragma unroll
            for (int u = 0; u < 4; ++u) {
                float4 vv = *(const float4*)(vr + u * 4);
                o[0][u].x += p0 * vv.x; o[0][u].y += p0 * vv.y; o[0][u].z += p0 * vv.z; o[0][u].w += p0 * vv.w;
                o[1][u].x += p1 * vv.x; o[1][u].y += p1 * vv.y; o[1][u].z += p1 * vv.z; o[1][u].w += p1 * vv.w;
                o[2][u].x += p2 * vv.x; o[2][u].y += p2 * vv.y; o[2][u].z += p2 * vv.z; o[2][u].w += p2 * vv.w;
                o[3][u].x += p3 * vv.x; o[3][u].y += p3 * vv.y; o[3][u].z += p3 * vv.z; o[3][u].w += p3 * vv.w;
            }
        }
    }

    // ---- epilogue: divide by l, vectorized store ----
#pragma unroll
    for (int i = 0; i < 4; ++i) {
        float inv = 1.f / l[i];
        float4* dst = (float4*)(O + ((size_t)b * Nn + qbase + ty * 4 + i) * Dd + tx * 16);
#pragma unroll
        for (int u = 0; u < 4; ++u) {
            float4 r = o[i][u];
            r.x *= inv; r.y *= inv; r.z *= inv; r.w *= inv;
            dst[u] = r;
        }
    }
}

// ---------------------------------------------------------------------------
extern "C" void kernel_launch(void* const* d_in, const int* in_sizes, int n_in,
                              void* d_out, int out_size) {
    const float* Q = (const float*)d_in[0];
    const float* K = (const float*)d_in[1];
    const float* V = (const float*)d_in[2];
    float* O = (float*)d_out;

    // 1) per-row inverse norms (one warp per row; 8 warps per 256-thread block)
    row_invnorm_kernel<<<(2 * Bb * Nn) / 8, 256>>>(Q, K);

    // 2) transpose + scale K into g_kt
    dim3 tg(Nn / 32, Dd / 32, Bb);
    transpose_scale_kernel<<<tg, dim3(32, 8, 1)>>>(K);

    // 3) flash attention
    int smem = (BM * QS + Dd * BN + BN * Dd + BM * PS) * (int)sizeof(float);  // 215040 B
    cudaFuncSetAttribute(attn_kernel, cudaFuncAttributeMaxDynamicSharedMemorySize, smem);
    attn_kernel<<<dim3(Nn / BM, Bb, 1), 256, smem>>>(Q, V, O);
}

// round 14
// speedup vs baseline: 8.8152x; 8.8152x over previous
#include <cuda_runtime.h>
#include <cuda_bf16.h>
#include <math.h>
#include <stdint.h>

#define Bb 4
#define Nn 4096
#define Dd 256
#define BM 128
#define BN 64
#define NT (Nn / BN)
#define SCALEF 0.17677669529663689f   // 32^-0.5; upper bound on all scores

// ---------------- device scratch (no allocation allowed) ----------------
__device__ float g_invq[Bb * Nn];
__device__ float g_invk[Bb * Nn];
__device__ __align__(16) __nv_bfloat16 g_qb[(size_t)Bb * Nn * Dd];    // normalized q * SCALE
__device__ __align__(16) __nv_bfloat16 g_kb[(size_t)Bb * Nn * Dd];    // normalized k
__device__ __align__(16) __nv_bfloat16 g_vthi[(size_t)Bb * Dd * Nn];  // V^T hi  [b][d][key]
__device__ __align__(16) __nv_bfloat16 g_vtlo[(size_t)Bb * Dd * Nn];  // V^T lo

// ---------------- helpers ----------------
__device__ __forceinline__ uint32_t s2u(const void* p) {
    uint32_t a;
    asm("{ .reg .u64 t; cvta.to.shared.u64 t, %1; cvt.u32.u64 %0, t; }" : "=r"(a) : "l"(p));
    return a;
}

#define CP_ASYNC16(dst, src) \
    asm volatile("cp.async.cg.shared.global [%0], [%1], 16;" :: "r"(dst), "l"(src))
#define CP_COMMIT() asm volatile("cp.async.commit_group;" ::: "memory")
#define CP_WAIT1()  asm volatile("cp.async.wait_group 1;" ::: "memory")

__device__ __forceinline__ void ldsm4(uint32_t& r0, uint32_t& r1, uint32_t& r2, uint32_t& r3,
                                      uint32_t addr) {
    asm volatile("ldmatrix.sync.aligned.m8n8.x4.shared.b16 {%0,%1,%2,%3}, [%4];"
                 : "=r"(r0), "=r"(r1), "=r"(r2), "=r"(r3) : "r"(addr));
}

__device__ __forceinline__ void mma16816(float* c, uint32_t a0, uint32_t a1, uint32_t a2,
                                         uint32_t a3, uint32_t b0, uint32_t b1) {
    asm volatile(
        "mma.sync.aligned.m16n8k16.row.col.f32.bf16.bf16.f32 "
        "{%0,%1,%2,%3}, {%4,%5,%6,%7}, {%8,%9}, {%0,%1,%2,%3};"
        : "+f"(c[0]), "+f"(c[1]), "+f"(c[2]), "+f"(c[3])
        : "r"(a0), "r"(a1), "r"(a2), "r"(a3), "r"(b0), "r"(b1));
}

// ---------------------------------------------------------------------------
// Prep 1: per-row inverse L2 norms (invq gets SCALE folded in)
// ---------------------------------------------------------------------------
__global__ void row_invnorm_kernel(const float* __restrict__ Q,
                                   const float* __restrict__ K) {
    int gw = (blockIdx.x * blockDim.x + threadIdx.x) >> 5;
    int lane = threadIdx.x & 31;
    if (gw >= 2 * Bb * Nn) return;
    bool isQ = gw < Bb * Nn;
    int row = isQ ? gw : gw - Bb * Nn;
    const float* src = (isQ ? Q : K) + (size_t)row * Dd;
    float ss = 0.f;
#pragma unroll
    for (int c = lane * 4; c < Dd; c += 128) {
        float4 v = *(const float4*)(src + c);
        ss += v.x * v.x + v.y * v.y + v.z * v.z + v.w * v.w;
    }
#pragma unroll
    for (int off = 16; off; off >>= 1) ss += __shfl_xor_sync(0xffffffffu, ss, off);
    if (lane == 0) {
        float inv = 1.f / fmaxf(sqrtf(ss), 1e-12f);
        if (isQ) g_invq[row] = inv * SCALEF;
        else     g_invk[row] = inv;
    }
}

// ---------------------------------------------------------------------------
// Prep 2: quantize q*invq*SCALE and k*invk to bf16
// ---------------------------------------------------------------------------
__global__ void quant_kernel(const float* __restrict__ Q, const float* __restrict__ K) {
    int gi = blockIdx.x * blockDim.x + threadIdx.x;
    const int total = Bb * Nn * Dd / 4;
    bool isQ = gi < total;
    int j = isQ ? gi : gi - total;
    int row = j >> 6;
    float s = isQ ? g_invq[row] : g_invk[row];
    float4 v = *(const float4*)((isQ ? Q : K) + (size_t)j * 4);
    __nv_bfloat162 a = __floats2bfloat162_rn(v.x * s, v.y * s);
    __nv_bfloat162 b = __floats2bfloat162_rn(v.z * s, v.w * s);
    uint2 pk;
    pk.x = *(uint32_t*)&a; pk.y = *(uint32_t*)&b;
    *(uint2*)((isQ ? g_qb : g_kb) + (size_t)j * 4) = pk;
}

// ---------------------------------------------------------------------------
// Prep 3: V[b][key][d] -> V^T hi/lo bf16 [b][d][key]
// ---------------------------------------------------------------------------
__global__ void vsplit_kernel(const float* __restrict__ V) {
    __shared__ float tile[32][33];
    int b = blockIdx.z, nb = blockIdx.x * 32, db = blockIdx.y * 32;
    int tx = threadIdx.x, ty = threadIdx.y;  // (32, 8)
#pragma unroll
    for (int j = 0; j < 32; j += 8)
        tile[ty + j][tx] = V[((size_t)b * Nn + nb + ty + j) * Dd + db + tx];
    __syncthreads();
#pragma unroll
    for (int j = 0; j < 32; j += 8) {
        int d = db + ty + j;
        float v = tile[tx][ty + j];
        __nv_bfloat16 hi = __float2bfloat16(v);
        __nv_bfloat16 lo = __float2bfloat16(v - __bfloat162float(hi));
        size_t o = ((size_t)b * Dd + d) * Nn + nb + tx;
        g_vthi[o] = hi;
        g_vtlo[o] = lo;
    }
}

// ---------------------------------------------------------------------------
// Attention kernel: mma.sync bf16, fixed-max softmax, P/V hi-lo compensated PV.
// 256 threads = 8 warps; warp w owns rows w*16..w*16+15 of the 128-row block.
// smem: Q 64KB | K double 2x32KB | V^T hi 32KB | V^T lo 32KB  = 192KB
// ---------------------------------------------------------------------------
#define SQ   0
#define SK   65536
#define SVH  131072
#define SVL  163840
#define SMEM_BYTES 196608

// cp.async K tile t into buffer kb (2048 16B chunks, 8 per thread)
__device__ __forceinline__ void cp_k_tile(uint32_t kb, int b, int t, int tid) {
    const __nv_bfloat16* src = g_kb + ((size_t)b * Nn + (size_t)t * BN) * Dd;
#pragma unroll
    for (int i = 0; i < 8; ++i) {
        int idx = tid + i * 256;
        int row = idx >> 5, c = idx & 31;
        uint32_t dst = kb + row * 512 + ((c ^ (row & 7)) << 4);
        CP_ASYNC16(dst, src + (size_t)row * Dd + c * 8);
    }
}

// cp.async V^T hi+lo tile t (2048 chunks each, 16 per thread total)
__device__ __forceinline__ void cp_v_tile(uint32_t sb, int b, int t, int tid) {
    const __nv_bfloat16* sh = g_vthi + (size_t)b * Dd * Nn + (size_t)t * BN;
    const __nv_bfloat16* sl = g_vtlo + (size_t)b * Dd * Nn + (size_t)t * BN;
#pragma unroll
    for (int i = 0; i < 8; ++i) {
        int idx = tid + i * 256;
        int row = idx >> 3, c = idx & 7;
        uint32_t off = row * 128 + ((c ^ (row & 7)) << 4);
        CP_ASYNC16(sb + SVH + off, sh + (size_t)row * Nn + c * 8);
        CP_ASYNC16(sb + SVL + off, sl + (size_t)row * Nn + c * 8);
    }
}

__global__ void __launch_bounds__(256, 1)
attn_mma_kernel(float* __restrict__ O) {
    extern __shared__ char smem[];
    uint32_t sb = s2u(smem);
    int tid = threadIdx.x, wid = tid >> 5, ln = tid & 31;
    int b = blockIdx.y;
    int qbase = blockIdx.x * BM;

    // ---- prologue: Q tile (swizzled), prefetch K0 then V0 ----
    {
        const __nv_bfloat16* qsrc = g_qb + ((size_t)b * Nn + qbase) * Dd;
#pragma unroll
        for (int i = 0; i < 16; ++i) {
            int idx = tid + i * 256;
            int row = idx >> 5, c = idx & 31;
            *(float4*)(smem + SQ + row * 512 + ((c ^ (row & 7)) << 4)) =
                *(const float4*)(qsrc + (size_t)row * Dd + c * 8);
        }
    }
    cp_k_tile(sb + SK, b, 0, tid);
    CP_COMMIT();
    cp_v_tile(sb, b, 0, tid);
    CP_COMMIT();

    float o[128];
#pragma unroll
    for (int i = 0; i < 128; ++i) o[i] = 0.f;
    float l0 = 0.f, l1 = 0.f;

    // per-thread invariant ldmatrix address pieces
    const int a_row = wid * 16 + (ln & 15);        // Q A-frag row
    const int a_ch0 = (ln >> 4);                    // + 2*kk
    const int bk_row_in = ((ln >> 4) << 3) + (ln & 7);  // B-frag row within 16
    const int bk_ch0 = ((ln >> 3) & 1);             // + 2*kk

    for (int t = 0; t < NT; ++t) {
        CP_WAIT1();            // K[t] ready (V[t] may still be in flight)
        __syncthreads();
        if (t + 1 < NT) cp_k_tile(sb + SK + ((t + 1) & 1) * 32768, b, t + 1, tid);
        CP_COMMIT();

        // ---- QK^T: S[16 x 64] per warp ----
        float s[32];
#pragma unroll
        for (int i = 0; i < 32; ++i) s[i] = 0.f;
        uint32_t kb = sb + SK + (t & 1) * 32768;
#pragma unroll 4
        for (int kk = 0; kk < 16; ++kk) {
            uint32_t a0, a1, a2, a3;
            {
                int ch = 2 * kk + a_ch0;
                ldsm4(a0, a1, a2, a3, sb + SQ + a_row * 512 + ((ch ^ (a_row & 7)) << 4));
            }
#pragma unroll
            for (int jp = 0; jp < 4; ++jp) {
                int row = jp * 16 + bk_row_in;
                int ch = 2 * kk + bk_ch0;
                uint32_t b0, b1, b2, b3;
                ldsm4(b0, b1, b2, b3, kb + row * 512 + ((ch ^ (row & 7)) << 4));
                mma16816(s + 8 * jp,     a0, a1, a2, a3, b0, b1);
                mma16816(s + 8 * jp + 4, a0, a1, a2, a3, b2, b3);
            }
        }

        CP_WAIT1();            // V[t] ready (K[t+1] may still be in flight)
        __syncthreads();

        // ---- softmax: p = exp(s - SCALE); accumulate row-partial l ----
#pragma unroll
        for (int j = 0; j < 8; ++j) {
            float p0 = __expf(s[4 * j]     - SCALEF);
            float p1 = __expf(s[4 * j + 1] - SCALEF);
            float p2 = __expf(s[4 * j + 2] - SCALEF);
            float p3 = __expf(s[4 * j + 3] - SCALEF);
            l0 += p0 + p1;
            l1 += p2 + p3;
            s[4 * j] = p0; s[4 * j + 1] = p1; s[4 * j + 2] = p2; s[4 * j + 3] = p3;
        }

        // ---- PV: O += Phi*Vhi + Phi*Vlo + Plo*Vhi ----
#pragma unroll
        for (int kk = 0; kk < 4; ++kk) {
            uint32_t ah[4], al[4];
#pragma unroll
            for (int u = 0; u < 4; ++u) {
                // u=0: (j0 row-lo) u=1: (j0 row-hi) u=2: (j1 row-lo) u=3: (j1 row-hi)
                int base = 8 * kk + (u >> 1) * 4 + (u & 1) * 2;
                float x = s[base], y = s[base + 1];
                __nv_bfloat162 h = __floats2bfloat162_rn(x, y);
                ah[u] = *(uint32_t*)&h;
                __nv_bfloat162 lo2 = __floats2bfloat162_rn(
                    x - __bfloat162float(h.x), y - __bfloat162float(h.y));
                al[u] = *(uint32_t*)&lo2;
            }
            // fix ordering: a1 must be row-hi of j0 -> indices (u mapping) below
            uint32_t A0 = ah[0], A1 = ah[1], A2 = ah[2], A3 = ah[3];
            uint32_t L0 = al[0], L1 = al[1], L2 = al[2], L3 = al[3];
#pragma unroll
            for (int jp = 0; jp < 16; ++jp) {
                int row = jp * 16 + bk_row_in;
                int ch = 2 * kk + bk_ch0;
                uint32_t off = row * 128 + ((ch ^ (row & 7)) << 4);
                uint32_t h0, h1, h2, h3, g0, g1, g2, g3;
                ldsm4(h0, h1, h2, h3, sb + SVH + off);
                ldsm4(g0, g1, g2, g3, sb + SVL + off);
                float* oj = o + 8 * jp;
                mma16816(oj, A0, A1, A2, A3, h0, h1);
                mma16816(oj, A0, A1, A2, A3, g0, g1);
                mma16816(oj, L0, L1, L2, L3, h0, h1);
                float* oj2 = o + 8 * jp + 4;
                mma16816(oj2, A0, A1, A2, A3, h2, h3);
                mma16816(oj2, A0, A1, A2, A3, g2, g3);
                mma16816(oj2, L0, L1, L2, L3, h2, h3);
            }
        }

        __syncthreads();       // all warps done reading V[t]
        if (t + 1 < NT) cp_v_tile(sb, b, t + 1, tid);
        CP_COMMIT();
    }

    // ---- epilogue: reduce l over the quad, scale, store ----
    l0 += __shfl_xor_sync(0xffffffffu, l0, 1);
    l0 += __shfl_xor_sync(0xffffffffu, l0, 2);
    l1 += __shfl_xor_sync(0xffffffffu, l1, 1);
    l1 += __shfl_xor_sync(0xffffffffu, l1, 2);
    float inv0 = 1.f / l0, inv1 = 1.f / l1;

    int row_lo = qbase + wid * 16 + (ln >> 2);
    int col0 = 2 * (ln & 3);
    float* orow0 = O + ((size_t)b * Nn + row_lo) * Dd + col0;
    float* orow1 = orow0 + 8 * (size_t)Dd;   // row_lo + 8
#pragma unroll
    for (int j = 0; j < 32; ++j) {
        float2 w0 = make_float2(o[4 * j] * inv0, o[4 * j + 1] * inv0);
        float2 w1 = make_float2(o[4 * j + 2] * inv1, o[4 * j + 3] * inv1);
        *(float2*)(orow0 + 8 * j) = w0;
        *(float2*)(orow1 + 8 * j) = w1;
    }
}

// ---------------------------------------------------------------------------
extern "C" void kernel_launch(void* const* d_in, const int* in_sizes, int n_in,
                              void* d_out, int out_size) {
    const float* Q = (const float*)d_in[0];
    const float* K = (const float*)d_in[1];
    const float* V = (const float*)d_in[2];
    float* O = (float*)d_out;

    row_invnorm_kernel<<<(2 * Bb * Nn) / 8, 256>>>(Q, K);
    quant_kernel<<<(2 * Bb * Nn * Dd / 4) / 256, 256>>>(Q, K);
    vsplit_kernel<<<dim3(Nn / 32, Dd / 32, Bb), dim3(32, 8, 1)>>>(V);

    cudaFuncSetAttribute(attn_mma_kernel, cudaFuncAttributeMaxDynamicSharedMemorySize, SMEM_BYTES);
    attn_mma_kernel<<<dim3(Nn / BM, Bb, 1), 256, SMEM_BYTES>>>(O);
}

// round 15
// speedup vs baseline: 14.8845x; 1.6885x over previous
#include <cuda_runtime.h>
#include <cuda_fp16.h>
#include <math.h>
#include <stdint.h>

#define Bb 4
#define Nn 4096
#define Dd 256
#define BM 128
#define BN 64
#define NT (Nn / BN)
#define SCALEF 0.17677669529663689f   // 32^-0.5; upper bound on |scores|
#define C0 0.84375f                   // P centering constant (exact in fp16)

// ---------------- device scratch (no allocation allowed) ----------------
__device__ __align__(16) __half g_qh[(size_t)Bb * Nn * Dd];   // normalized q * SCALE
__device__ __align__(16) __half g_kh[(size_t)Bb * Nn * Dd];   // normalized k
__device__ __align__(16) __half g_vth[(size_t)Bb * Dd * Nn];  // V^T fp16 [b][d][key]
__device__ float g_vpart[(size_t)Bb * 128 * Dd];              // colsum partials per 32-key block
__device__ float g_vsum[Bb * Dd];                             // colsum(V) per (b,d)

// ---------------- helpers ----------------
__device__ __forceinline__ uint32_t s2u(const void* p) {
    uint32_t a;
    asm("{ .reg .u64 t; cvta.to.shared.u64 t, %1; cvt.u32.u64 %0, t; }" : "=r"(a) : "l"(p));
    return a;
}

#define CP_ASYNC16(dst, src) \
    asm volatile("cp.async.cg.shared.global [%0], [%1], 16;" :: "r"(dst), "l"(src))
#define CP_COMMIT() asm volatile("cp.async.commit_group;" ::: "memory")
#define CP_WAIT1()  asm volatile("cp.async.wait_group 1;" ::: "memory")

__device__ __forceinline__ void ldsm4(uint32_t& r0, uint32_t& r1, uint32_t& r2, uint32_t& r3,
                                      uint32_t addr) {
    asm volatile("ldmatrix.sync.aligned.m8n8.x4.shared.b16 {%0,%1,%2,%3}, [%4];"
                 : "=r"(r0), "=r"(r1), "=r"(r2), "=r"(r3) : "r"(addr));
}

__device__ __forceinline__ void mma16816(float* c, uint32_t a0, uint32_t a1, uint32_t a2,
                                         uint32_t a3, uint32_t b0, uint32_t b1) {
    asm volatile(
        "mma.sync.aligned.m16n8k16.row.col.f32.f16.f16.f32 "
        "{%0,%1,%2,%3}, {%4,%5,%6,%7}, {%8,%9}, {%0,%1,%2,%3};"
        : "+f"(c[0]), "+f"(c[1]), "+f"(c[2]), "+f"(c[3])
        : "r"(a0), "r"(a1), "r"(a2), "r"(a3), "r"(b0), "r"(b1));
}

__device__ __forceinline__ uint32_t pkh2(float x, float y) {
    __half2 h = __floats2half2_rn(x, y);
    return *(uint32_t*)&h;
}

// ---------------------------------------------------------------------------
// Prep 1 (fused): per-row inverse L2 norm + fp16 quantize, one warp per row.
// Row data stays in registers: load -> reduce -> scale -> store fp16.
// ---------------------------------------------------------------------------
__global__ void norm_quant_kernel(const float* __restrict__ Q,
                                  const float* __restrict__ K) {
    int gw = (blockIdx.x * blockDim.x + threadIdx.x) >> 5;
    int lane = threadIdx.x & 31;
    bool isQ = gw < Bb * Nn;
    int row = isQ ? gw : gw - Bb * Nn;
    const float* src = (isQ ? Q : K) + (size_t)row * Dd;

    float4 v0 = *(const float4*)(src + lane * 4);
    float4 v1 = *(const float4*)(src + lane * 4 + 128);
    float ss = v0.x * v0.x + v0.y * v0.y + v0.z * v0.z + v0.w * v0.w +
               v1.x * v1.x + v1.y * v1.y + v1.z * v1.z + v1.w * v1.w;
#pragma unroll
    for (int off = 16; off; off >>= 1) ss += __shfl_xor_sync(0xffffffffu, ss, off);
    float s = 1.f / fmaxf(sqrtf(ss), 1e-12f);
    if (isQ) s *= SCALEF;

    __half* dst = (isQ ? g_qh : g_kh) + (size_t)row * Dd;
    uint2 a, b;
    a.x = pkh2(v0.x * s, v0.y * s); a.y = pkh2(v0.z * s, v0.w * s);
    b.x = pkh2(v1.x * s, v1.y * s); b.y = pkh2(v1.z * s, v1.w * s);
    *(uint2*)(dst + lane * 4)       = a;
    *(uint2*)(dst + lane * 4 + 128) = b;
}

// ---------------------------------------------------------------------------
// Prep 2: V[b][key][d] -> V^T fp16 [b][d][key], plus per-32-key-block colsums
// ---------------------------------------------------------------------------
__global__ void vtrans_kernel(const float* __restrict__ V) {
    __shared__ float tile[32][33];
    int b = blockIdx.z, nb = blockIdx.x * 32, db = blockIdx.y * 32;
    int tx = threadIdx.x, ty = threadIdx.y;  // (32, 8)
#pragma unroll
    for (int j = 0; j < 32; j += 8)
        tile[ty + j][tx] = V[((size_t)b * Nn + nb + ty + j) * Dd + db + tx];
    __syncthreads();
#pragma unroll
    for (int j = 0; j < 32; j += 8) {
        int d = db + ty + j;
        g_vth[((size_t)b * Dd + d) * Nn + nb + tx] = __float2half(tile[tx][ty + j]);
    }
    // deterministic partial colsum: 32 threads (ty==0), one d each
    if (ty == 0) {
        float s = 0.f;
#pragma unroll
        for (int k = 0; k < 32; ++k) s += tile[k][tx];
        g_vpart[((size_t)b * 128 + blockIdx.x) * Dd + db + tx] = s;
    }
}

__global__ void vsum_reduce_kernel() {
    int b = blockIdx.x, d = threadIdx.x;
    float s = 0.f;
#pragma unroll 8
    for (int i = 0; i < 128; ++i) s += g_vpart[((size_t)b * 128 + i) * Dd + d];
    g_vsum[b * Dd + d] = s;
}

// ---------------------------------------------------------------------------
// Attention: fp16 mma.sync, fixed-max softmax, centered P (single PV GEMM),
// rank-1 colsum correction at epilogue.
// 256 threads = 8 warps; warp w owns rows w*16..w*16+15 of the 128-row block.
// smem: Q 64KB | K double 2x32KB | V^T 32KB = 160KB
// ---------------------------------------------------------------------------
#define SQ   0
#define SK   65536
#define SVH  131072
#define SMEM_BYTES 163840

__device__ __forceinline__ void cp_k_tile(uint32_t kb, int b, int t, int tid) {
    const __half* src = g_kh + ((size_t)b * Nn + (size_t)t * BN) * Dd;
#pragma unroll
    for (int i = 0; i < 8; ++i) {
        int idx = tid + i * 256;
        int row = idx >> 5, c = idx & 31;
        CP_ASYNC16(kb + row * 512 + ((c ^ (row & 7)) << 4), src + (size_t)row * Dd + c * 8);
    }
}

__device__ __forceinline__ void cp_v_tile(uint32_t sb, int b, int t, int tid) {
    const __half* sh = g_vth + (size_t)b * Dd * Nn + (size_t)t * BN;
#pragma unroll
    for (int i = 0; i < 8; ++i) {
        int idx = tid + i * 256;
        int row = idx >> 3, c = idx & 7;
        CP_ASYNC16(sb + SVH + row * 128 + ((c ^ (row & 7)) << 4), sh + (size_t)row * Nn + c * 8);
    }
}

__global__ void __launch_bounds__(256, 1)
attn_mma_kernel(float* __restrict__ O) {
    extern __shared__ char smem[];
    uint32_t sb = s2u(smem);
    int tid = threadIdx.x, wid = tid >> 5, ln = tid & 31;
    int b = blockIdx.y;
    int qbase = blockIdx.x * BM;

    // ---- prologue: Q tile (swizzled), prefetch K0 then V0 ----
    {
        const __half* qsrc = g_qh + ((size_t)b * Nn + qbase) * Dd;
#pragma unroll
        for (int i = 0; i < 16; ++i) {
            int idx = tid + i * 256;
            int row = idx >> 5, c = idx & 31;
            *(float4*)(smem + SQ + row * 512 + ((c ^ (row & 7)) << 4)) =
                *(const float4*)(qsrc + (size_t)row * Dd + c * 8);
        }
    }
    cp_k_tile(sb + SK, b, 0, tid);
    CP_COMMIT();
    cp_v_tile(sb, b, 0, tid);
    CP_COMMIT();

    float o[128];
#pragma unroll
    for (int i = 0; i < 128; ++i) o[i] = 0.f;
    float l0 = 0.f, l1 = 0.f;

    const int a_row = wid * 16 + (ln & 15);
    const int a_ch0 = (ln >> 4);
    const int bk_row_in = ((ln >> 4) << 3) + (ln & 7);
    const int bk_ch0 = ((ln >> 3) & 1);

    for (int t = 0; t < NT; ++t) {
        CP_WAIT1();            // K[t] ready (V[t] may still be in flight)
        __syncthreads();
        if (t + 1 < NT) cp_k_tile(sb + SK + ((t + 1) & 1) * 32768, b, t + 1, tid);
        CP_COMMIT();

        // ---- QK^T: S[16 x 64] per warp ----
        float s[32];
#pragma unroll
        for (int i = 0; i < 32; ++i) s[i] = 0.f;
        uint32_t kb = sb + SK + (t & 1) * 32768;
#pragma unroll 4
        for (int kk = 0; kk < 16; ++kk) {
            uint32_t a0, a1, a2, a3;
            {
                int ch = 2 * kk + a_ch0;
                ldsm4(a0, a1, a2, a3, sb + SQ + a_row * 512 + ((ch ^ (a_row & 7)) << 4));
            }
#pragma unroll
            for (int jp = 0; jp < 4; ++jp) {
                int row = jp * 16 + bk_row_in;
                int ch = 2 * kk + bk_ch0;
                uint32_t b0, b1, b2, b3;
                ldsm4(b0, b1, b2, b3, kb + row * 512 + ((ch ^ (row & 7)) << 4));
                mma16816(s + 8 * jp,     a0, a1, a2, a3, b0, b1);
                mma16816(s + 8 * jp + 4, a0, a1, a2, a3, b2, b3);
            }
        }

        CP_WAIT1();            // V[t] ready (K[t+1] may still be in flight)
        __syncthreads();

        // ---- softmax: p = exp(s - SCALE); l += p; store c = p - C0 ----
#pragma unroll
        for (int j = 0; j < 8; ++j) {
            float p0 = __expf(s[4 * j]     - SCALEF);
            float p1 = __expf(s[4 * j + 1] - SCALEF);
            float p2 = __expf(s[4 * j + 2] - SCALEF);
            float p3 = __expf(s[4 * j + 3] - SCALEF);
            l0 += p0 + p1;
            l1 += p2 + p3;
            s[4 * j]     = p0 - C0;
            s[4 * j + 1] = p1 - C0;
            s[4 * j + 2] = p2 - C0;
            s[4 * j + 3] = p3 - C0;
        }

        // ---- PV: O += C * V^T   (single fp16 GEMM) ----
#pragma unroll
        for (int kk = 0; kk < 4; ++kk) {
            uint32_t A0, A1, A2, A3;
            {
                int base = 8 * kk;
                A0 = pkh2(s[base],     s[base + 1]);
                A1 = pkh2(s[base + 2], s[base + 3]);
                A2 = pkh2(s[base + 4], s[base + 5]);
                A3 = pkh2(s[base + 6], s[base + 7]);
            }
#pragma unroll
            for (int jp = 0; jp < 16; ++jp) {
                int row = jp * 16 + bk_row_in;
                int ch = 2 * kk + bk_ch0;
                uint32_t h0, h1, h2, h3;
                ldsm4(h0, h1, h2, h3, sb + SVH + row * 128 + ((ch ^ (row & 7)) << 4));
                mma16816(o + 8 * jp,     A0, A1, A2, A3, h0, h1);
                mma16816(o + 8 * jp + 4, A0, A1, A2, A3, h2, h3);
            }
        }

        __syncthreads();       // all warps done reading V[t]
        if (t + 1 < NT) cp_v_tile(sb, b, t + 1, tid);
        CP_COMMIT();
    }

    // ---- epilogue: quad-reduce l, add C0*colsum(V), normalize, store ----
    l0 += __shfl_xor_sync(0xffffffffu, l0, 1);
    l0 += __shfl_xor_sync(0xffffffffu, l0, 2);
    l1 += __shfl_xor_sync(0xffffffffu, l1, 1);
    l1 += __shfl_xor_sync(0xffffffffu, l1, 2);
    float inv0 = 1.f / l0, inv1 = 1.f / l1;

    int row_lo = qbase + wid * 16 + (ln >> 2);
    int col0 = 2 * (ln & 3);
    const float* vs = g_vsum + b * Dd + col0;
    float* orow0 = O + ((size_t)b * Nn + row_lo) * Dd + col0;
    float* orow1 = orow0 + 8 * (size_t)Dd;   // row_lo + 8
#pragma unroll
    for (int j = 0; j < 32; ++j) {
        float2 sv = *(const float2*)(vs + 8 * j);
        float n0 = o[4 * j]     + C0 * sv.x;
        float n1 = o[4 * j + 1] + C0 * sv.y;
        float n2 = o[4 * j + 2] + C0 * sv.x;
        float n3 = o[4 * j + 3] + C0 * sv.y;
        *(float2*)(orow0 + 8 * j) = make_float2(n0 * inv0, n1 * inv0);
        *(float2*)(orow1 + 8 * j) = make_float2(n2 * inv1, n3 * inv1);
    }
}

// ---------------------------------------------------------------------------
extern "C" void kernel_launch(void* const* d_in, const int* in_sizes, int n_in,
                              void* d_out, int out_size) {
    const float* Q = (const float*)d_in[0];
    const float* K = (const float*)d_in[1];
    const float* V = (const float*)d_in[2];
    float* O = (float*)d_out;

    norm_quant_kernel<<<(2 * Bb * Nn) / 8, 256>>>(Q, K);
    vtrans_kernel<<<dim3(Nn / 32, Dd / 32, Bb), dim3(32, 8, 1)>>>(V);
    vsum_reduce_kernel<<<Bb, Dd>>>();

    cudaFuncSetAttribute(attn_mma_kernel, cudaFuncAttributeMaxDynamicSharedMemorySize, SMEM_BYTES);
    attn_mma_kernel<<<dim3(Nn / BM, Bb, 1), 256, SMEM_BYTES>>>(O);
}